// round 1
// baseline (speedup 1.0000x reference)
#include <cuda_runtime.h>
#include <math.h>

// ---------------- problem constants ----------------
#define NN 100000
#define NE 1600000
#define IN_CH 128

// ---------------- scratch (device globals; no allocation) ----------------
__device__ float g_xW1[(size_t)NN * 64];
__device__ float g_alS1[(size_t)NN * 8];
__device__ float g_alD1[(size_t)NN * 8];
__device__ float g_h1[(size_t)NN * 64];
__device__ float g_xW2[(size_t)NN * 64];
__device__ float g_alS2[NN];
__device__ float g_alD2[NN];
__device__ float g_h2[(size_t)NN * 64];
__device__ float g_h3[(size_t)NN * 64];
__device__ float g_A[(size_t)NN * 128];
__device__ float g_B[(size_t)NN * 128];
__device__ int   g_deg[NN];
__device__ int   g_roff[NN + 1];
__device__ int   g_cur[NN];
__device__ int   g_csrc[NE];

// ---------------- small node GEMM: Y[M,NC] = X[M,K] @ W[K,NC] (+bias) ----------------
// BM=128 rows/block, BK=32, 256 threads, each thread TM=4 rows x TNC cols.
// EPI: 0 = none; 1 = per-head logits (NC=64, 8 heads x 8): alS[row*8+h]=dot(acc,aS[h]);
//      2 = full-row logits (NC=64): alS[row]=dot(full row, aS) via 8-lane shuffle reduce.
template<int K, int NC, int EPI>
__global__ __launch_bounds__(256)
void node_gemm_kernel(const float* __restrict__ X,
                      const float* __restrict__ W,
                      const float* __restrict__ bias,
                      const float* __restrict__ aS,
                      const float* __restrict__ aD,
                      float* __restrict__ Y,
                      float* __restrict__ alS,
                      float* __restrict__ alD,
                      int n)
{
    constexpr int BM = 128, BK = 32;
    constexpr int TNC = (NC == 64) ? 8 : 16;
    constexpr int TM = 4;
    __shared__ float Xs[BK][BM];
    __shared__ float Ws[BK][NC];

    const int t   = threadIdx.x;
    const int tc  = t & 7;    // 8 col-groups
    const int tr  = t >> 3;   // 32 row-groups
    const int row0 = blockIdx.x * BM;
    const bool has_bias = (bias != nullptr);

    float acc[TM][TNC];
#pragma unroll
    for (int i = 0; i < TM; i++)
#pragma unroll
        for (int j = 0; j < TNC; j++) acc[i][j] = 0.0f;

    for (int k0 = 0; k0 < K; k0 += BK) {
        __syncthreads();
        // load X tile (transposed into Xs[k][row])
        for (int i = t; i < BM * BK / 4; i += 256) {
            int r = i >> 3;
            int kk = (i & 7) * 4;
            int grow = row0 + r;
            float4 v = make_float4(0.f, 0.f, 0.f, 0.f);
            if (grow < n) v = *(const float4*)(X + (size_t)grow * K + k0 + kk);
            Xs[kk + 0][r] = v.x; Xs[kk + 1][r] = v.y;
            Xs[kk + 2][r] = v.z; Xs[kk + 3][r] = v.w;
        }
        // load W tile
        for (int i = t; i < BK * NC / 4; i += 256) {
            int r = i / (NC / 4);
            int c = (i % (NC / 4)) * 4;
            *(float4*)&Ws[r][c] = *(const float4*)(W + (size_t)(k0 + r) * NC + c);
        }
        __syncthreads();
#pragma unroll
        for (int k = 0; k < BK; k++) {
            float xv[TM];
#pragma unroll
            for (int i = 0; i < TM; i++) xv[i] = Xs[k][tr * TM + i];
#pragma unroll
            for (int j4 = 0; j4 < TNC; j4 += 4) {
                float4 w4 = *(const float4*)&Ws[k][tc * TNC + j4];
#pragma unroll
                for (int i = 0; i < TM; i++) {
                    acc[i][j4 + 0] += xv[i] * w4.x;
                    acc[i][j4 + 1] += xv[i] * w4.y;
                    acc[i][j4 + 2] += xv[i] * w4.z;
                    acc[i][j4 + 3] += xv[i] * w4.w;
                }
            }
        }
    }

    // epilogue
#pragma unroll
    for (int i = 0; i < TM; i++) {
        int row = row0 + tr * TM + i;
        bool ok = (row < n);
        float outv[TNC];
#pragma unroll
        for (int j = 0; j < TNC; j++) {
            float v = acc[i][j];
            if (has_bias) v += bias[tc * TNC + j];
            outv[j] = v;
        }
        if (ok) {
            float* yrow = Y + (size_t)row * NC + tc * TNC;
#pragma unroll
            for (int j4 = 0; j4 < TNC; j4 += 4)
                *(float4*)(yrow + j4) = make_float4(outv[j4], outv[j4 + 1], outv[j4 + 2], outv[j4 + 3]);
        }
        if constexpr (EPI == 1) {
            // head = tc; a vectors are [8][8]
            float pS = 0.f, pD = 0.f;
#pragma unroll
            for (int j = 0; j < TNC; j++) {
                pS += acc[i][j] * aS[tc * 8 + j];
                pD += acc[i][j] * aD[tc * 8 + j];
            }
            if (ok) {
                alS[(size_t)row * 8 + tc] = pS;
                alD[(size_t)row * 8 + tc] = pD;
            }
        }
        if constexpr (EPI == 2) {
            float pS = 0.f, pD = 0.f;
#pragma unroll
            for (int j = 0; j < TNC; j++) {
                pS += acc[i][j] * aS[tc * 8 + j];
                pD += acc[i][j] * aD[tc * 8 + j];
            }
            // reduce across the 8 lanes sharing this row (contiguous lanes, tc = lane&7)
#pragma unroll
            for (int d = 4; d; d >>= 1) {
                pS += __shfl_down_sync(0xffffffffu, pS, d);
                pD += __shfl_down_sync(0xffffffffu, pD, d);
            }
            if (ok && tc == 0) {
                alS[row] = pS;
                alD[row] = pD;
            }
        }
    }
}

// ---------------- CSR build ----------------
__global__ void zero_int_kernel(int* __restrict__ p, int n)
{
    int i = blockIdx.x * blockDim.x + threadIdx.x;
    if (i < n) p[i] = 0;
}

__global__ void hist_kernel(const int* __restrict__ ei, int* __restrict__ deg, int E)
{
    int e = blockIdx.x * blockDim.x + threadIdx.x;
    if (e < E) atomicAdd(&deg[ei[E + e]], 1);   // dst
}

__global__ __launch_bounds__(1024)
void scan_kernel(const int* __restrict__ deg, int* __restrict__ roff,
                 int* __restrict__ cur, int n)
{
    __shared__ int wsum[32];
    int t = threadIdx.x, lane = t & 31, wid = t >> 5;
    int carry = 0;
    for (int base = 0; base < n; base += 1024) {
        int idx = base + t;
        int v = (idx < n) ? deg[idx] : 0;
        int incl = v;
#pragma unroll
        for (int d = 1; d < 32; d <<= 1) {
            int u = __shfl_up_sync(0xffffffffu, incl, d);
            if (lane >= d) incl += u;
        }
        if (lane == 31) wsum[wid] = incl;
        __syncthreads();
        if (wid == 0) {
            int s = wsum[lane];
#pragma unroll
            for (int d = 1; d < 32; d <<= 1) {
                int u = __shfl_up_sync(0xffffffffu, s, d);
                if (lane >= d) s += u;
            }
            wsum[lane] = s;
        }
        __syncthreads();
        int blockincl = incl + (wid ? wsum[wid - 1] : 0);
        int total = wsum[31];
        if (idx < n) {
            int ex = carry + blockincl - v;
            roff[idx] = ex;
            cur[idx]  = ex;
        }
        carry += total;
        __syncthreads();
    }
    if (t == 0) roff[n] = carry;
}

__global__ void scatter_kernel(const int* __restrict__ ei, int* __restrict__ cur,
                               int* __restrict__ csrc, int E)
{
    int e = blockIdx.x * blockDim.x + threadIdx.x;
    if (e < E) {
        int d = ei[E + e];
        int p = atomicAdd(&cur[d], 1);
        csrc[p] = ei[e];
    }
}

// ---------------- GAT aggregation (warp per destination node) ----------------
// out[i] = elu( (sum_e w_e * xW[src_e]) / (sum_e w_e) + bias ), w = exp(leaky(alS[src]+alD[i]))
template<int HEADS>
__global__ __launch_bounds__(256)
void gat_agg_kernel(const float* __restrict__ xW,
                    const float* __restrict__ alS,
                    const float* __restrict__ alD,
                    const int* __restrict__ roff,
                    const int* __restrict__ csrc,
                    const float* __restrict__ bias,
                    float* __restrict__ out, int n)
{
    int warp = (blockIdx.x * blockDim.x + threadIdx.x) >> 5;
    if (warp >= n) return;
    int l = threadIdx.x & 31;
    int i = warp;
    int h = (HEADS == 8) ? (l >> 2) : 0;
    float ald = alD[(size_t)i * HEADS + h];
    float accx = 0.f, accy = 0.f, ws = 0.f;
    int e0 = roff[i], e1 = roff[i + 1];
    for (int j = e0; j < e1; j++) {
        int s = csrc[j];
        float e = alS[(size_t)s * HEADS + h] + ald;
        float w = __expf(fmaxf(e, 0.2f * e));
        float2 v = *(const float2*)(xW + (size_t)s * 64 + 2 * l);
        accx += w * v.x; accy += w * v.y; ws += w;
    }
    {   // self loop
        float e = alS[(size_t)i * HEADS + h] + ald;
        float w = __expf(fmaxf(e, 0.2f * e));
        float2 v = *(const float2*)(xW + (size_t)i * 64 + 2 * l);
        accx += w * v.x; accy += w * v.y; ws += w;
    }
    float inv = 1.0f / ws;
    float o0 = accx * inv + bias[2 * l];
    float o1 = accy * inv + bias[2 * l + 1];
    // ELU
    o0 = (o0 > 0.f) ? o0 : (__expf(o0) - 1.0f);
    o1 = (o1 > 0.f) ? o1 : (__expf(o1) - 1.0f);
    float2* orow = (float2*)(out + (size_t)i * 64 + 2 * l);
    *orow = make_float2(o0, o1);
}

// ---------------- edge MLP (warp per edge) ----------------
// pre[128] = A[src] + B[dst] + edge_attr @ Wc   (A already contains mlp_b1)
// eo = relu(pre) @ W2 + b2 ; out = log_softmax(eo)
__global__ __launch_bounds__(256)
void edge_mlp_kernel(const int* __restrict__ ei,
                     const float* __restrict__ eattr,
                     const float* __restrict__ A,
                     const float* __restrict__ B,
                     const float* __restrict__ W1c,  // [16][128]
                     const float* __restrict__ W2,   // [128][2]
                     const float* __restrict__ b2,
                     float* __restrict__ out, int E)
{
    __shared__ float  Wc[16][128];
    __shared__ float2 W2s[128];
    __shared__ float  b2s[2];
    int t = threadIdx.x;
    for (int i = t; i < 16 * 128; i += 256) Wc[i >> 7][i & 127] = W1c[i];
    for (int i = t; i < 128; i += 256) W2s[i] = make_float2(W2[i * 2], W2[i * 2 + 1]);
    if (t < 2) b2s[t] = b2[t];
    __syncthreads();

    int e = (int)((blockIdx.x * 256 + t) >> 5);
    if (e >= E) return;
    int l = t & 31;
    int src = ei[e];
    int dst = ei[E + e];

    float4 a4 = *(const float4*)(A + (size_t)src * 128 + 4 * l);
    float4 b4 = *(const float4*)(B + (size_t)dst * 128 + 4 * l);
    float p0 = a4.x + b4.x, p1 = a4.y + b4.y, p2 = a4.z + b4.z, p3 = a4.w + b4.w;

    float eav = (l < 16) ? eattr[(size_t)e * 16 + l] : 0.f;
#pragma unroll
    for (int k = 0; k < 16; k++) {
        float ek = __shfl_sync(0xffffffffu, eav, k);
        float4 w4 = *(const float4*)&Wc[k][4 * l];
        p0 += ek * w4.x; p1 += ek * w4.y; p2 += ek * w4.z; p3 += ek * w4.w;
    }
    p0 = fmaxf(p0, 0.f); p1 = fmaxf(p1, 0.f); p2 = fmaxf(p2, 0.f); p3 = fmaxf(p3, 0.f);

    float2 c0 = W2s[4 * l + 0], c1 = W2s[4 * l + 1], c2 = W2s[4 * l + 2], c3 = W2s[4 * l + 3];
    float s0 = p0 * c0.x + p1 * c1.x + p2 * c2.x + p3 * c3.x;
    float s1 = p0 * c0.y + p1 * c1.y + p2 * c2.y + p3 * c3.y;
#pragma unroll
    for (int d = 16; d; d >>= 1) {
        s0 += __shfl_xor_sync(0xffffffffu, s0, d);
        s1 += __shfl_xor_sync(0xffffffffu, s1, d);
    }
    if (l == 0) {
        float eo0 = s0 + b2s[0];
        float eo1 = s1 + b2s[1];
        float m = fmaxf(eo0, eo1);
        float lse = m + log1pf(__expf(fminf(eo0, eo1) - m));
        float2* op = (float2*)(out + (size_t)e * 2);
        *op = make_float2(eo0 - lse, eo1 - lse);
    }
}

// ---------------- launcher ----------------
extern "C" void kernel_launch(void* const* d_in, const int* in_sizes, int n_in,
                              void* d_out, int out_size)
{
    const float* x        = (const float*)d_in[0];
    const int*   ei       = (const int*)  d_in[1];
    const float* eattr    = (const float*)d_in[2];
    const float* W1       = (const float*)d_in[3];
    const float* a_src1   = (const float*)d_in[4];
    const float* a_dst1   = (const float*)d_in[5];
    const float* b1       = (const float*)d_in[6];
    const float* W2       = (const float*)d_in[7];
    const float* a_src2   = (const float*)d_in[8];
    const float* a_dst2   = (const float*)d_in[9];
    const float* b2       = (const float*)d_in[10];
    const float* lin_W    = (const float*)d_in[11];
    const float* lin_b    = (const float*)d_in[12];
    const float* mlp_W1   = (const float*)d_in[13];
    const float* mlp_b1   = (const float*)d_in[14];
    const float* mlp_W2   = (const float*)d_in[15];
    const float* mlp_b2   = (const float*)d_in[16];
    float* outp = (float*)d_out;

    const int n = in_sizes[0] / IN_CH;       // 100000
    const int E = in_sizes[1] / 2;           // 1600000

    float *p_xW1, *p_alS1, *p_alD1, *p_h1, *p_xW2, *p_alS2, *p_alD2, *p_h2, *p_h3, *p_A, *p_B;
    int *p_deg, *p_roff, *p_cur, *p_csrc;
    cudaGetSymbolAddress((void**)&p_xW1,  g_xW1);
    cudaGetSymbolAddress((void**)&p_alS1, g_alS1);
    cudaGetSymbolAddress((void**)&p_alD1, g_alD1);
    cudaGetSymbolAddress((void**)&p_h1,   g_h1);
    cudaGetSymbolAddress((void**)&p_xW2,  g_xW2);
    cudaGetSymbolAddress((void**)&p_alS2, g_alS2);
    cudaGetSymbolAddress((void**)&p_alD2, g_alD2);
    cudaGetSymbolAddress((void**)&p_h2,   g_h2);
    cudaGetSymbolAddress((void**)&p_h3,   g_h3);
    cudaGetSymbolAddress((void**)&p_A,    g_A);
    cudaGetSymbolAddress((void**)&p_B,    g_B);
    cudaGetSymbolAddress((void**)&p_deg,  g_deg);
    cudaGetSymbolAddress((void**)&p_roff, g_roff);
    cudaGetSymbolAddress((void**)&p_cur,  g_cur);
    cudaGetSymbolAddress((void**)&p_csrc, g_csrc);

    const int gemm_blocks = (n + 127) / 128;
    const int agg_blocks  = (n * 32 + 255) / 256;
    const int e_blocks    = (E + 255) / 256;
    const int mlp_blocks  = (int)(((size_t)E * 32 + 255) / 256);

    // CSR build (independent of GEMM1; interleave for overlap)
    zero_int_kernel<<<(n + 255) / 256, 256>>>(p_deg, n);
    hist_kernel<<<e_blocks, 256>>>(ei, p_deg, E);

    // GEMM1: xW1 = x@W1, attention logits per head
    node_gemm_kernel<128, 64, 1><<<gemm_blocks, 256>>>(
        x, W1, nullptr, a_src1, a_dst1, p_xW1, p_alS1, p_alD1, n);

    scan_kernel<<<1, 1024>>>(p_deg, p_roff, p_cur, n);
    scatter_kernel<<<e_blocks, 256>>>(ei, p_cur, p_csrc, E);

    // GAT layer 1 aggregation -> h1 (bias + ELU fused)
    gat_agg_kernel<8><<<agg_blocks, 256>>>(p_xW1, p_alS1, p_alD1, p_roff, p_csrc, b1, p_h1, n);

    // GEMM2: xW2 = h1@W2, scalar logits (heads=1)
    node_gemm_kernel<64, 64, 2><<<gemm_blocks, 256>>>(
        p_h1, W2, nullptr, a_src2, a_dst2, p_xW2, p_alS2, p_alD2, n);

    // GAT layer 2 aggregation -> h2
    gat_agg_kernel<1><<<agg_blocks, 256>>>(p_xW2, p_alS2, p_alD2, p_roff, p_csrc, b2, p_h2, n);

    // h3 = h2 @ lin_W + lin_b
    node_gemm_kernel<64, 64, 0><<<gemm_blocks, 256>>>(
        p_h2, lin_W, lin_b, nullptr, nullptr, p_h3, nullptr, nullptr, n);

    // A = h3 @ Wa + mlp_b1 ; B = h3 @ Wb   (Wa = mlp_W1 rows 0..63, Wb = rows 64..127)
    node_gemm_kernel<64, 128, 0><<<gemm_blocks, 256>>>(
        p_h3, mlp_W1, mlp_b1, nullptr, nullptr, p_A, nullptr, nullptr, n);
    node_gemm_kernel<64, 128, 0><<<gemm_blocks, 256>>>(
        p_h3, mlp_W1 + (size_t)64 * 128, nullptr, nullptr, nullptr, p_B, nullptr, nullptr, n);

    // edge MLP + log_softmax (Wc = mlp_W1 rows 128..143)
    edge_mlp_kernel<<<mlp_blocks, 256>>>(
        ei, eattr, p_A, p_B, mlp_W1 + (size_t)128 * 128, mlp_W2, mlp_b2, outp, E);
}